// round 7
// baseline (speedup 1.0000x reference)
#include <cuda_runtime.h>
#include <cuda_bf16.h>

// Problem constants
#define S 8192
#define D 1024
#define E 64
#define CAP 128
#define SHIFT 4096
static const long long SEC = (long long)S * E * CAP;   // 67108864

#define CB 128                      // compute blocks (gemm + routing chain)
#define FB 512                      // dedicated fill blocks
#define FSLOTS ((long long)FB * 256)
#define CSLOTS ((long long)CB * 256)
// out_size = 134217794 floats. finalize owns floats {0} U [134217729, 134217794).
// fill owns float4 idx [1, 33554432) == floats [4,134217728), plus floats {1,2,3,134217728}.
#define F4_LO  1LL
#define F4_MID 27262976LL           // fill-block share [F4_LO, F4_MID)
#define F4_HI  33554432LL           // compute-block share [F4_MID, F4_HI)

// ---------------- scratch (device globals) ----------------------------------
__device__ float g_gmax[S];
__device__ int   g_expert_at_p[S];
__device__ int   g_token_at_p[S];
__device__ int   g_hist[S];          // [128 chunks][64 experts]; reset by launch B
__device__ int   g_choff[S];
__device__ float g_me_part[CB * E];
__device__ int   g_cnt_part[CB * E];
__device__ unsigned g_c1, g_c2;      // spin-barrier counters; reset by launch B

// ---------------------------------------------------------------------------
// Launch A: blocks 0..127: GEMM + softmax + rank + position + prefix, then fill
//           blocks 128..639: continuous zero-fill
// ---------------------------------------------------------------------------
__global__ void __launch_bounds__(256, 5)
kA(const float* __restrict__ x, const float* __restrict__ w,
   float* __restrict__ out) {
    __shared__ float sbuf[4160];            // As/Bs (4096) alias L[64][65] alias rank chunk
    __shared__ float smax[64], sinv[64];
    __shared__ int   sbeste[64], sranks[64];
    __shared__ int   scnt[E];
    __shared__ int   spart[4 * 64];
    const int tid = threadIdx.x;
    float4* o4 = (float4*)out;
    const float4 z = make_float4(0.f, 0.f, 0.f, 0.f);

    if (blockIdx.x < CB) {
        // ---------------- GEMM: BM=64, BN=64, BK=32, 4x4 micro-tile ---------
        float (*As)[64] = (float(*)[64])sbuf;          // [32][64]
        float (*Bs)[64] = (float(*)[64])(sbuf + 2048); // [32][64]
        const int m0 = blockIdx.x * 64;
        const int tx = tid & 15;
        const int ty = tid >> 4;
        float acc[4][4];
        #pragma unroll
        for (int i = 0; i < 4; i++)
            #pragma unroll
            for (int j = 0; j < 4; j++) acc[i][j] = 0.0f;

        for (int k0 = 0; k0 < D; k0 += 32) {
            #pragma unroll
            for (int r = 0; r < 8; r++) {
                int l  = tid + r * 256;
                int mm = l & 63;
                int kk = l >> 6;
                As[kk][mm] = x[(long long)(m0 + mm) * D + k0 + kk];
                Bs[kk][mm] = w[(long long)mm * D + k0 + kk];
            }
            __syncthreads();
            #pragma unroll
            for (int kk = 0; kk < 32; kk++) {
                const float4 a = *(const float4*)(&As[kk][ty * 4]);
                const float4 b = *(const float4*)(&Bs[kk][tx * 4]);
                float av[4] = {a.x, a.y, a.z, a.w};
                float bv[4] = {b.x, b.y, b.z, b.w};
                #pragma unroll
                for (int i = 0; i < 4; i++)
                    #pragma unroll
                    for (int j = 0; j < 4; j++)
                        acc[i][j] += av[i] * bv[j];
            }
            __syncthreads();
        }

        // ---------------- epilogue: softmax / argmax ------------------------
        float* L = sbuf;                    // [64][65]
        #pragma unroll
        for (int i = 0; i < 4; i++)
            #pragma unroll
            for (int j = 0; j < 4; j++)
                L[(ty * 4 + i) * 65 + tx * 4 + j] = acc[i][j];
        if (tid < E) scnt[tid] = 0;
        __syncthreads();

        if (tid < 64) {
            const int t = tid;
            float bv = L[t * 65];
            int   bi = 0;
            #pragma unroll 8
            for (int e = 1; e < E; e++) {
                float v = L[t * 65 + e];
                if (v > bv) { bv = v; bi = e; }
            }
            float ssum = 0.0f;
            #pragma unroll 8
            for (int e = 0; e < E; e++) ssum += expf(L[t * 65 + e] - bv);
            float inv = 1.0f / ssum;
            smax[t] = bv;
            sinv[t] = inv;                   // == max gate
            sbeste[t] = bi;
            g_gmax[m0 + t] = inv;
            atomicAdd(&scnt[bi], 1);
        }
        __syncthreads();
        if (tid < E) {
            const int e = tid;
            float me = 0.0f;
            #pragma unroll 8
            for (int t = 0; t < 64; t++)
                me += expf(L[t * 65 + e] - smax[t]) * sinv[t];
            g_me_part[blockIdx.x * E + e]  = me;
            g_cnt_part[blockIdx.x * E + e] = scnt[e];
        }

        // ---------------- barrier 1: all gmax visible -----------------------
        __threadfence();
        __syncthreads();
        if (tid == 0) {
            atomicAdd(&g_c1, 1u);
            while (atomicAdd(&g_c1, 0u) < (unsigned)CB) {}
        }
        __syncthreads();

        // ---------------- rank (stable argsort of -gmax, counting) ----------
        // 4 threads per token; gmax staged in smem chunks of 2048
        const int tok  = tid >> 2;
        const int part = tid & 3;
        const int tg   = m0 + tok;
        const float gt = sinv[tok];
        int cnt = 0;
        for (int c = 0; c < 4; c++) {
            __syncthreads();
            for (int i = tid; i < 2048; i += 256)
                sbuf[i] = __ldcg(&g_gmax[c * 2048 + i]);
            __syncthreads();
            #pragma unroll 8
            for (int i = 0; i < 512; i++) {
                int j = part * 512 + ((i + part * 8) & 511);
                int u = c * 2048 + j;
                float v = sbuf[j];
                cnt += (u < tg) ? (v >= gt) : (v > gt);
            }
        }
        cnt += __shfl_down_sync(0xffffffff, cnt, 1);
        cnt += __shfl_down_sync(0xffffffff, cnt, 2);
        if (part == 0) sranks[tok] = cnt;
        __syncthreads();

        // ---------------- position (roll) + global histogram ----------------
        if (tid < 64) {
            int p = (sranks[tid] + SHIFT) & (S - 1);
            int e = sbeste[tid];
            g_expert_at_p[p] = e;
            g_token_at_p[p]  = m0 + tid;
            atomicAdd(&g_hist[(p >> 6) * E + e], 1);
        }

        // ---------------- barrier 2 arrival (only block 0 waits) ------------
        __threadfence();
        __syncthreads();
        if (tid == 0) atomicAdd(&g_c2, 1u);

        if (blockIdx.x == 0) {
            if (tid == 0) { while (atomicAdd(&g_c2, 0u) < (unsigned)CB) {} }
            __syncthreads();
            // prefix: per-expert exclusive scan over 128 chunks
            const int e = tid & 63, q = tid >> 6;   // 64 experts x 4 quarters
            int v[32];
            int sum = 0;
            #pragma unroll
            for (int i = 0; i < 32; i++) {
                v[i] = __ldcg(&g_hist[((q * 32 + i) << 6) + e]);
                sum += v[i];
            }
            spart[q * 64 + e] = sum;
            __syncthreads();
            int run = 0;
            for (int qq = 0; qq < q; qq++) run += spart[qq * 64 + e];
            #pragma unroll
            for (int i = 0; i < 32; i++) {
                g_choff[((q * 32 + i) << 6) + e] = run;
                run += v[i];
            }
        }

        // ---------------- join fill: [F4_MID, F4_HI) ------------------------
        for (long long i = F4_MID + (long long)blockIdx.x * 256 + tid;
             i < F4_HI; i += CSLOTS) o4[i] = z;
    } else {
        // ---------------- dedicated fill: [F4_LO, F4_MID) -------------------
        const int fb = blockIdx.x - CB;
        for (long long i = F4_LO + (long long)fb * 256 + tid;
             i < F4_MID; i += FSLOTS) o4[i] = z;
        if (fb == 0 && tid < 3) out[1 + tid] = 0.0f;
        if (fb == 0 && tid == 3) out[134217728] = 0.0f;
    }
}

// ---------------------------------------------------------------------------
// Launch B: blocks 0..127: per-chunk rank + sparse scatter (+ reset hist)
//           block 128: finalize scalars/counts (+ reset barrier counters)
// ---------------------------------------------------------------------------
__global__ void kB(float* __restrict__ out) {
    if (blockIdx.x < 128) {
        __shared__ int se[64];
        const int i = threadIdx.x;
        const int p = blockIdx.x * 64 + i;
        const int e = g_expert_at_p[p];
        const int t = g_token_at_p[p];
        se[i] = e;
        __syncthreads();
        int c = 0;
        for (int j = 0; j < i; j++) c += (se[j] == e);
        const int loc = g_choff[blockIdx.x * E + e] + c;
        if (loc < CAP) {
            long long base = 1LL + ((long long)t * E + e) * CAP + loc;
            out[base]       = g_gmax[t];  // combine_weights
            out[base + SEC] = 1.0f;       // dispatch_mask
        }
        g_hist[blockIdx.x * 64 + i] = 0;  // reset for next replay
    } else {
        __shared__ float red[E];
        __shared__ int   sc[E];
        const int e = threadIdx.x;
        float me = 0.0f;
        int   c  = 0;
        #pragma unroll 8
        for (int b = 0; b < CB; b++) {
            me += g_me_part[b * E + e];
            c  += g_cnt_part[b * E + e];
        }
        const float inv = 1.0f / (float)S;
        red[e] = (me * inv) * ((float)c * inv);
        sc[e]  = c;
        out[1LL + 2LL * SEC + e] = (float)c;
        __syncthreads();
        if (e == 0) {
            float sum = 0.0f;
            int dropped = 0;
            for (int k = 0; k < E; k++) {
                sum += red[k];
                int d = sc[k] - CAP;
                if (d > 0) dropped += d;
            }
            out[0] = sum * (float)E * 0.01f;
            out[1LL + 2LL * SEC + E] = (float)dropped * inv;
            g_c1 = 0;                    // reset barriers for next replay
            g_c2 = 0;
        }
    }
}

// ---------------------------------------------------------------------------
extern "C" void kernel_launch(void* const* d_in, const int* in_sizes, int n_in,
                              void* d_out, int out_size) {
    const float* x = (const float*)d_in[0];   // [S, D]
    const float* w = (const float*)d_in[1];   // [E, D]
    float* out = (float*)d_out;

    kA<<<CB + FB, 256>>>(x, w, out);
    kB<<<129, 64>>>(out);
}

// round 8
// speedup vs baseline: 1.0630x; 1.0630x over previous
#include <cuda_runtime.h>
#include <cuda_bf16.h>

// Problem constants
#define S 8192
#define D 1024
#define E 64
#define CAP 128
#define SHIFT 4096
static const long long SEC = (long long)S * E * CAP;   // 67108864

#define CB 128                      // compute blocks (gemm + routing chain)
#define FB 1024                     // dedicated fill blocks (R2-proven config)
#define FSLOTS ((long long)FB * 256)

// ---------------- scratch (device globals) ----------------------------------
__device__ float g_gmax[S];
__device__ int   g_expert_at_p[S];
__device__ int   g_token_at_p[S];
__device__ int   g_hist[S];          // [128 chunks][64 experts]; reset by kB
__device__ int   g_choff[S];
__device__ float g_me_part[CB * E];
__device__ int   g_cnt_part[CB * E];
__device__ unsigned g_c1, g_c2;      // spin-barrier counters; reset by kB

// ---------------------------------------------------------------------------
// kA: blocks 0..127   : GEMM + softmax + rank + position + prefix (then exit)
//     blocks 128..1151: grid-stride zero-fill of the whole output (R2 style)
// ---------------------------------------------------------------------------
__global__ void __launch_bounds__(256)
kA(const float* __restrict__ x, const float* __restrict__ w,
   float* __restrict__ out, long long out_size) {
    __shared__ float sbuf[4160];            // As/Bs (4096) alias L[64][65] alias rank chunk
    __shared__ float smax[64], sinv[64];
    __shared__ int   sbeste[64], sranks[64];
    __shared__ int   scnt[E];
    __shared__ int   spart[4 * 64];
    const int tid = threadIdx.x;

    if (blockIdx.x >= CB) {
        // ---------------- dedicated fill: whole buffer (proven R2 path) -----
        long long n4 = out_size >> 2;
        float4* o4 = (float4*)out;
        const float4 z = make_float4(0.f, 0.f, 0.f, 0.f);
        long long idx = (long long)(blockIdx.x - CB) * 256 + tid;
        for (; idx < n4; idx += FSLOTS) o4[idx] = z;
        if (blockIdx.x == CB) {
            for (long long i = (n4 << 2) + tid; i < out_size; i += 256)
                out[i] = 0.0f;
        }
        return;
    }

    // ---------------- GEMM: BM=64, BN=64, BK=32, 4x4 micro-tile -------------
    float (*As)[64] = (float(*)[64])sbuf;          // [32][64]
    float (*Bs)[64] = (float(*)[64])(sbuf + 2048); // [32][64]
    const int m0 = blockIdx.x * 64;
    const int tx = tid & 15;
    const int ty = tid >> 4;
    float acc[4][4];
    #pragma unroll
    for (int i = 0; i < 4; i++)
        #pragma unroll
        for (int j = 0; j < 4; j++) acc[i][j] = 0.0f;

    for (int k0 = 0; k0 < D; k0 += 32) {
        #pragma unroll
        for (int r = 0; r < 8; r++) {
            int l  = tid + r * 256;
            int mm = l & 63;
            int kk = l >> 6;
            As[kk][mm] = x[(long long)(m0 + mm) * D + k0 + kk];
            Bs[kk][mm] = w[(long long)mm * D + k0 + kk];
        }
        __syncthreads();
        #pragma unroll
        for (int kk = 0; kk < 32; kk++) {
            const float4 a = *(const float4*)(&As[kk][ty * 4]);
            const float4 b = *(const float4*)(&Bs[kk][tx * 4]);
            float av[4] = {a.x, a.y, a.z, a.w};
            float bv[4] = {b.x, b.y, b.z, b.w};
            #pragma unroll
            for (int i = 0; i < 4; i++)
                #pragma unroll
                for (int j = 0; j < 4; j++)
                    acc[i][j] += av[i] * bv[j];
        }
        __syncthreads();
    }

    // ---------------- epilogue: softmax / argmax ----------------------------
    float* L = sbuf;                    // [64][65]
    #pragma unroll
    for (int i = 0; i < 4; i++)
        #pragma unroll
        for (int j = 0; j < 4; j++)
            L[(ty * 4 + i) * 65 + tx * 4 + j] = acc[i][j];
    if (tid < E) scnt[tid] = 0;
    __syncthreads();

    if (tid < 64) {
        const int t = tid;
        float bv = L[t * 65];
        int   bi = 0;
        #pragma unroll 8
        for (int e = 1; e < E; e++) {
            float v = L[t * 65 + e];
            if (v > bv) { bv = v; bi = e; }
        }
        float ssum = 0.0f;
        #pragma unroll 8
        for (int e = 0; e < E; e++) ssum += expf(L[t * 65 + e] - bv);
        float inv = 1.0f / ssum;
        smax[t] = bv;
        sinv[t] = inv;                   // == max gate
        sbeste[t] = bi;
        g_gmax[m0 + t] = inv;
        atomicAdd(&scnt[bi], 1);
    }
    __syncthreads();
    if (tid < E) {
        const int e = tid;
        float me = 0.0f;
        #pragma unroll 8
        for (int t = 0; t < 64; t++)
            me += expf(L[t * 65 + e] - smax[t]) * sinv[t];
        g_me_part[blockIdx.x * E + e]  = me;
        g_cnt_part[blockIdx.x * E + e] = scnt[e];
    }

    // ---------------- barrier 1: all gmax visible ---------------------------
    __threadfence();
    __syncthreads();
    if (tid == 0) {
        atomicAdd(&g_c1, 1u);
        while (atomicAdd(&g_c1, 0u) < (unsigned)CB) {}
    }
    __syncthreads();

    // ---------------- rank (stable argsort of -gmax, counting) --------------
    // 4 threads per token; gmax staged in smem chunks of 2048
    const int tok  = tid >> 2;
    const int part = tid & 3;
    const int tg   = m0 + tok;
    const float gt = sinv[tok];
    int cnt = 0;
    for (int c = 0; c < 4; c++) {
        __syncthreads();
        for (int i = tid; i < 2048; i += 256)
            sbuf[i] = __ldcg(&g_gmax[c * 2048 + i]);
        __syncthreads();
        #pragma unroll 8
        for (int i = 0; i < 512; i++) {
            int j = part * 512 + ((i + part * 8) & 511);
            int u = c * 2048 + j;
            float v = sbuf[j];
            cnt += (u < tg) ? (v >= gt) : (v > gt);
        }
    }
    cnt += __shfl_down_sync(0xffffffff, cnt, 1);
    cnt += __shfl_down_sync(0xffffffff, cnt, 2);
    if (part == 0) sranks[tok] = cnt;
    __syncthreads();

    // ---------------- position (roll) + global histogram --------------------
    if (tid < 64) {
        int p = (sranks[tid] + SHIFT) & (S - 1);
        int e = sbeste[tid];
        g_expert_at_p[p] = e;
        g_token_at_p[p]  = m0 + tid;
        atomicAdd(&g_hist[(p >> 6) * E + e], 1);
    }

    // ---------------- barrier 2 arrival (only block 0 waits) ----------------
    __threadfence();
    __syncthreads();
    if (tid == 0) atomicAdd(&g_c2, 1u);

    if (blockIdx.x == 0) {
        if (tid == 0) { while (atomicAdd(&g_c2, 0u) < (unsigned)CB) {} }
        __syncthreads();
        // prefix: per-expert exclusive scan over 128 chunks
        const int e = tid & 63, q = tid >> 6;   // 64 experts x 4 quarters
        int v[32];
        int sum = 0;
        #pragma unroll
        for (int i = 0; i < 32; i++) {
            v[i] = __ldcg(&g_hist[((q * 32 + i) << 6) + e]);
            sum += v[i];
        }
        spart[q * 64 + e] = sum;
        __syncthreads();
        int run = 0;
        for (int qq = 0; qq < q; qq++) run += spart[qq * 64 + e];
        #pragma unroll
        for (int i = 0; i < 32; i++) {
            g_choff[((q * 32 + i) << 6) + e] = run;
            run += v[i];
        }
    }
}

// ---------------------------------------------------------------------------
// kB: blocks 0..127: per-chunk rank + sparse scatter (+ reset hist)
//     block 128: finalize scalars/counts (+ reset barrier counters)
// ---------------------------------------------------------------------------
__global__ void kB(float* __restrict__ out) {
    if (blockIdx.x < 128) {
        __shared__ int se[64];
        const int i = threadIdx.x;
        const int p = blockIdx.x * 64 + i;
        const int e = g_expert_at_p[p];
        const int t = g_token_at_p[p];
        se[i] = e;
        __syncthreads();
        int c = 0;
        for (int j = 0; j < i; j++) c += (se[j] == e);
        const int loc = g_choff[blockIdx.x * E + e] + c;
        if (loc < CAP) {
            long long base = 1LL + ((long long)t * E + e) * CAP + loc;
            out[base]       = g_gmax[t];  // combine_weights
            out[base + SEC] = 1.0f;       // dispatch_mask
        }
        g_hist[blockIdx.x * 64 + i] = 0;  // reset for next replay
    } else {
        __shared__ float red[E];
        __shared__ int   sc[E];
        const int e = threadIdx.x;
        float me = 0.0f;
        int   c  = 0;
        #pragma unroll 8
        for (int b = 0; b < CB; b++) {
            me += g_me_part[b * E + e];
            c  += g_cnt_part[b * E + e];
        }
        const float inv = 1.0f / (float)S;
        red[e] = (me * inv) * ((float)c * inv);
        sc[e]  = c;
        out[1LL + 2LL * SEC + e] = (float)c;
        __syncthreads();
        if (e == 0) {
            float sum = 0.0f;
            int dropped = 0;
            for (int k = 0; k < E; k++) {
                sum += red[k];
                int d = sc[k] - CAP;
                if (d > 0) dropped += d;
            }
            out[0] = sum * (float)E * 0.01f;
            out[1LL + 2LL * SEC + E] = (float)dropped * inv;
            g_c1 = 0;                    // reset barriers for next replay
            g_c2 = 0;
        }
    }
}

// ---------------------------------------------------------------------------
extern "C" void kernel_launch(void* const* d_in, const int* in_sizes, int n_in,
                              void* d_out, int out_size) {
    const float* x = (const float*)d_in[0];   // [S, D]
    const float* w = (const float*)d_in[1];   // [E, D]
    float* out = (float*)d_out;

    kA<<<CB + FB, 256>>>(x, w, out, (long long)out_size);
    kB<<<129, 64>>>(out);
}

// round 9
// speedup vs baseline: 1.4561x; 1.3698x over previous
#include <cuda_runtime.h>
#include <cuda_bf16.h>

// Problem constants
#define S 8192
#define D 1024
#define E 64
#define CAP 128
#define SHIFT 4096
#define RANK_Y 8
static const long long SEC = (long long)S * E * CAP;   // 67108864

#define GEMM_BLOCKS 128
#define ZERO_BLOCKS 1024

// ---------------- scratch (device globals; no cross-call state) -------------
__device__ int   g_beste[S];
__device__ float g_gmax[S];
__device__ int   g_rank_part[RANK_Y * S];
__device__ int   g_expert_at_p[S];
__device__ int   g_token_at_p[S];
__device__ int   g_choff[S];                 // [128 chunks][64 experts] excl prefix
__device__ float g_me_part[GEMM_BLOCKS * E];
__device__ int   g_cnt_part[GEMM_BLOCKS * E];

// ---------------------------------------------------------------------------
// K1: blocks 0..127 : GEMM (64 tokens x 64 experts) + softmax epilogue
//     blocks 128..  : grid-stride zero-fill of the whole output (proven R2)
// ---------------------------------------------------------------------------
__global__ void k1_fused(const float* __restrict__ x,
                         const float* __restrict__ w,
                         float* __restrict__ out, long long out_size) {
    const int tid = threadIdx.x;

    if (blockIdx.x < GEMM_BLOCKS) {
        __shared__ float sbuf[64 * 65];           // As/Bs alias + logits L[64][65]
        float (*As)[64] = (float(*)[64])sbuf;          // [32][64]
        float (*Bs)[64] = (float(*)[64])(sbuf + 2048); // [32][64]
        __shared__ float smax[64], sinv[64];
        __shared__ int   scnt[E];

        const int m0 = blockIdx.x * 64;
        const int tx = tid & 15;
        const int ty = tid >> 4;
        float acc[4][4];
        #pragma unroll
        for (int i = 0; i < 4; i++)
            #pragma unroll
            for (int j = 0; j < 4; j++) acc[i][j] = 0.0f;

        for (int k0 = 0; k0 < D; k0 += 32) {
            #pragma unroll
            for (int r = 0; r < 8; r++) {
                int l  = tid + r * 256;
                int mm = l & 63;
                int kk = l >> 6;
                As[kk][mm] = x[(long long)(m0 + mm) * D + k0 + kk];
                Bs[kk][mm] = w[(long long)mm * D + k0 + kk];
            }
            __syncthreads();
            #pragma unroll
            for (int kk = 0; kk < 32; kk++) {
                const float4 a = *(const float4*)(&As[kk][ty * 4]);
                const float4 b = *(const float4*)(&Bs[kk][tx * 4]);
                float av[4] = {a.x, a.y, a.z, a.w};
                float bv[4] = {b.x, b.y, b.z, b.w};
                #pragma unroll
                for (int i = 0; i < 4; i++)
                    #pragma unroll
                    for (int j = 0; j < 4; j++)
                        acc[i][j] += av[i] * bv[j];
            }
            __syncthreads();
        }

        float* L = sbuf;                           // [64][65] padded
        #pragma unroll
        for (int i = 0; i < 4; i++)
            #pragma unroll
            for (int j = 0; j < 4; j++)
                L[(ty * 4 + i) * 65 + tx * 4 + j] = acc[i][j];
        if (tid < E) scnt[tid] = 0;
        __syncthreads();

        if (tid < 64) {
            const int t = tid;
            float bv = L[t * 65];
            int   bi = 0;
            #pragma unroll 8
            for (int e = 1; e < E; e++) {
                float v = L[t * 65 + e];
                if (v > bv) { bv = v; bi = e; }
            }
            float s = 0.0f;
            #pragma unroll 8
            for (int e = 0; e < E; e++) s += expf(L[t * 65 + e] - bv);
            float inv = 1.0f / s;
            smax[t] = bv;
            sinv[t] = inv;
            g_beste[m0 + t] = bi;
            g_gmax[m0 + t]  = inv;                 // max gate = 1/sum
            atomicAdd(&scnt[bi], 1);
        }
        __syncthreads();
        if (tid < E) {
            const int e = tid;
            float me = 0.0f;
            #pragma unroll 8
            for (int t = 0; t < 64; t++)
                me += expf(L[t * 65 + e] - smax[t]) * sinv[t];
            g_me_part[blockIdx.x * E + e]  = me;
            g_cnt_part[blockIdx.x * E + e] = scnt[e];
        }
    } else {
        // ---- zero-fill the whole output buffer (poisoned to 0xAA) ----
        long long n4 = out_size >> 2;
        float4* o4 = (float4*)out;
        const float4 z = make_float4(0.f, 0.f, 0.f, 0.f);
        long long idx    = (long long)(blockIdx.x - GEMM_BLOCKS) * blockDim.x + tid;
        long long stride = (long long)ZERO_BLOCKS * blockDim.x;
        for (; idx < n4; idx += stride) o4[idx] = z;
        if (blockIdx.x == GEMM_BLOCKS) {
            for (long long i = (n4 << 2) + tid; i < out_size; i += blockDim.x)
                out[i] = 0.0f;
        }
    }
}

// ---------------------------------------------------------------------------
// K2: rank by counting (stable argsort of -gmax), partitioned over 8 u-slices
// ---------------------------------------------------------------------------
__global__ void k_rank() {
    __shared__ float sh[1024];
    const int t = blockIdx.x * 256 + threadIdx.x;
    const int ubase = blockIdx.y * 1024;
    for (int i = threadIdx.x; i < 1024; i += 256) sh[i] = g_gmax[ubase + i];
    __syncthreads();
    const float g = g_gmax[t];
    int lo = t - ubase;
    if (lo < 0) lo = 0;
    if (lo > 1024) lo = 1024;
    int cnt = 0;
    for (int j = 0; j < lo; j++)    cnt += (sh[j] >= g);
    for (int j = lo; j < 1024; j++) cnt += (sh[j] >  g);
    g_rank_part[blockIdx.y * S + t] = cnt;
}

// ---------------------------------------------------------------------------
// K3: position (roll), scatter expert/token by position, smem histogram,
//     per-expert exclusive prefix over 128 chunks. Single block, 1024 thr.
// ---------------------------------------------------------------------------
__global__ void k_pospfx() {
    __shared__ int hist[128 * E];                 // 32 KB
    const int tid = threadIdx.x;
    for (int i = tid; i < 128 * E; i += 1024) hist[i] = 0;
    __syncthreads();
    #pragma unroll
    for (int k = 0; k < 8; k++) {
        const int t = tid + k * 1024;
        int r = 0;
        #pragma unroll
        for (int y = 0; y < RANK_Y; y++) r += g_rank_part[y * S + t];
        const int p = (r + SHIFT) & (S - 1);
        const int e = g_beste[t];
        g_expert_at_p[p] = e;
        g_token_at_p[p]  = t;
        atomicAdd(&hist[(p >> 6) * E + e], 1);
    }
    __syncthreads();
    if (tid < E) {
        int run = 0;
        #pragma unroll 1
        for (int b = 0; b < 128; b++) {
            g_choff[b * E + tid] = run;
            run += hist[b * E + tid];
        }
    }
}

// ---------------------------------------------------------------------------
// K4: blocks 0..7 : ballot-based scatter (16 chunks of 64 per block, 1024 thr)
//     block 8     : parallel tree-reduce finalize
// ---------------------------------------------------------------------------
__global__ void k_scatfin(float* __restrict__ out) {
    const int tid = threadIdx.x;
    if (blockIdx.x < 8) {
        __shared__ int h0[16 * 64];            // per-chunk warp0 expert counts
        const int chunk = tid >> 6;            // 0..15
        const int lane  = tid & 31;
        const int half  = (tid >> 5) & 1;      // warp parity within chunk
        const int gchunk = blockIdx.x * 16 + chunk;
        const int p = gchunk * 64 + (tid & 63);
        const int e = g_expert_at_p[p];
        const int t = g_token_at_p[p];
        h0[tid] = 0;
        __syncthreads();
        unsigned mask = __match_any_sync(0xffffffffu, e);
        int below = __popc(mask & ((1u << lane) - 1u));
        if (half == 0 && lane == (int)(__ffs(mask) - 1))
            h0[chunk * 64 + e] = __popc(mask);
        __syncthreads();
        int c = below + (half ? h0[chunk * 64 + e] : 0);
        const int loc = g_choff[gchunk * E + e] + c;
        if (loc < CAP) {
            long long base = 1LL + ((long long)t * E + e) * CAP + loc;
            out[base]       = g_gmax[t];  // combine_weights
            out[base + SEC] = 1.0f;       // dispatch_mask
        }
    } else {
        // finalize: tree reduce of 128x64 partials with 1024 threads
        __shared__ float sme[16][64];
        __shared__ int   scn[16][64];
        const int e = tid & 63;
        const int g = tid >> 6;                // 0..15 groups of 8 blocks
        float me = 0.0f;
        int   c  = 0;
        #pragma unroll
        for (int i = 0; i < 8; i++) {
            int b = g * 8 + i;
            me += g_me_part[b * E + e];
            c  += g_cnt_part[b * E + e];
        }
        sme[g][e] = me;
        scn[g][e] = c;
        __syncthreads();
        const float inv = 1.0f / (float)S;
        if (tid < E) {
            float m = 0.0f;
            int  cc = 0;
            #pragma unroll
            for (int gg = 0; gg < 16; gg++) { m += sme[gg][tid]; cc += scn[gg][tid]; }
            sme[0][tid] = (m * inv) * ((float)cc * inv);
            scn[0][tid] = cc;
            out[1LL + 2LL * SEC + tid] = (float)cc;
        }
        __syncthreads();
        if (tid == 0) {
            float sum = 0.0f;
            int dropped = 0;
            for (int k = 0; k < E; k++) {
                sum += sme[0][k];
                int d = scn[0][k] - CAP;
                if (d > 0) dropped += d;
            }
            out[0] = sum * (float)E * 0.01f;
            out[1LL + 2LL * SEC + E] = (float)dropped * inv;
        }
    }
}

// ---------------------------------------------------------------------------
extern "C" void kernel_launch(void* const* d_in, const int* in_sizes, int n_in,
                              void* d_out, int out_size) {
    const float* x = (const float*)d_in[0];   // [S, D]
    const float* w = (const float*)d_in[1];   // [E, D]
    float* out = (float*)d_out;
    long long osz = (long long)out_size;

    k1_fused<<<GEMM_BLOCKS + ZERO_BLOCKS, 256>>>(x, w, out, osz);
    k_rank<<<dim3(S / 256, RANK_Y), 256>>>();
    k_pospfx<<<1, 1024>>>();
    k_scatfin<<<9, 1024>>>(out);
}